// round 3
// baseline (speedup 1.0000x reference)
#include <cuda_runtime.h>
#include <cstdint>

#define NN 40000        // nodes
#define NE 640000       // edges
#define D 128
#define D2 256
#define LTOK 10
#define NLAYERS 5
#define GG 512          // graphs
#define BN_EPS 1e-5f
#define STATS_BLKS 157  // ceil(NN/256)

// ---------------- scratch (static device globals; no allocation) ----------------
__device__ float g_h[NN * D];          // node features (post-BN each layer)
__device__ float g_z[NN * D];          // h + aggr accumulator
__device__ float g_mid[NN * D2];       // GIN MLP hidden
__device__ float g_z2[NN * D];         // GIN MLP output (pre-BN)
__device__ float g_part[STATS_BLKS * 2 * D];  // per-block BN partial sums
__device__ float g_mu[D];
__device__ float g_rsig[D];
__device__ float g_gsum[GG * D];
__device__ float g_gcnt[GG];

// ---------------- WordBag: h[n] = mean_l word_emb[tok[n,l]] ----------------
__global__ void wordbag_kernel(const int* __restrict__ x_tokens,
                               const int* __restrict__ ins_len,
                               const float* __restrict__ wemb) {
    int n = blockIdx.x;
    int d = threadIdx.x;
    __shared__ int toks[LTOK];
    __shared__ int len_s;
    if (d < LTOK) toks[d] = x_tokens[n * LTOK + d];
    if (d == 0) len_s = ins_len[n];
    __syncthreads();
    int len = len_s;
    float acc = 0.f;
    for (int l = 0; l < len; l++)
        acc += wemb[(long)toks[l] * D + d];
    float v = acc / (float)len;
    g_h[n * D + d] = v;
    g_z[n * D + d] = v;    // init z = h for layer 0
}

// ---------------- pool prep ----------------
__global__ void zero_pool_kernel() {
    int i = blockIdx.x * blockDim.x + threadIdx.x;
    if (i < GG * D) g_gsum[i] = 0.f;
    if (i < GG) g_gcnt[i] = 0.f;
}

__global__ void count_kernel(const int* __restrict__ batch_ids) {
    int i = blockIdx.x * blockDim.x + threadIdx.x;
    if (i < NN) atomicAdd(&g_gcnt[batch_ids[i]], 1.0f);
}

// ---------------- edge scatter: z[dst] += h[src] + edge_emb[edge_attr] ----------------
__global__ void scatter_kernel(const int* __restrict__ edge_index,
                               const int* __restrict__ edge_attr,
                               const float* __restrict__ eemb) {
    int warp = (blockIdx.x * blockDim.x + threadIdx.x) >> 5;
    int lane = threadIdx.x & 31;
    if (warp >= NE) return;
    int src = edge_index[warp];
    int dst = edge_index[NE + warp];
    int et  = edge_attr[warp];
    const float4* h4 = (const float4*)(g_h + (long)src * D);
    const float4* e4 = (const float4*)(eemb + et * D);
    float4 hv = h4[lane];
    float4 ev = e4[lane];
    float4 m;
    m.x = hv.x + ev.x; m.y = hv.y + ev.y; m.z = hv.z + ev.z; m.w = hv.w + ev.w;
    float* zp = g_z + (long)dst * D + lane * 4;
    asm volatile("red.global.add.v4.f32 [%0], {%1,%2,%3,%4};"
                 :: "l"(zp), "f"(m.x), "f"(m.y), "f"(m.z), "f"(m.w) : "memory");
}

// ---------------- 3xTF32 split-precision tensor-core GEMM ----------------
// C[M,NC] = act(A[M,K] @ W[K,NC] + bias), BM=64 BN=64 BK=32, 128 threads (4 warps 2x2)
// a = a_hi + a_lo (both tf32); C ~= Ahi*Bhi + Ahi*Blo + Alo*Bhi  (~22-bit mantissa)
#define TS 72   // smem row stride (8 mod 32 -> conflict-free fragment reads)
__device__ __forceinline__ uint32_t f2tf32(float v) {
    uint32_t u;
    asm("cvt.rna.tf32.f32 %0, %1;" : "=r"(u) : "f"(v));
    return u;
}

#define MMA_TF32(ACC, A0, A1, A2, A3, B0, B1)                                  \
    asm volatile(                                                              \
        "mma.sync.aligned.m16n8k8.row.col.f32.tf32.tf32.f32 "                  \
        "{%0,%1,%2,%3}, {%4,%5,%6,%7}, {%8,%9}, {%0,%1,%2,%3};"                \
        : "+f"(ACC[0]), "+f"(ACC[1]), "+f"(ACC[2]), "+f"(ACC[3])               \
        : "r"(A0), "r"(A1), "r"(A2), "r"(A3), "r"(B0), "r"(B1))

__global__ void gemm_3xtf32_kernel(const float* __restrict__ A, const float* __restrict__ W,
                                   const float* __restrict__ bias, float* __restrict__ C,
                                   int K, int NC, int do_relu) {
    __shared__ uint32_t AsH[32 * TS], AsL[32 * TS];   // [k][m] hi / lo
    __shared__ uint32_t BsH[32 * TS], BsL[32 * TS];   // [k][n] hi / lo
    int tid  = threadIdx.x;
    int lane = tid & 31;
    int warp = tid >> 5;
    int wm = warp >> 1, wn = warp & 1;   // warp tile (wm*32, wn*32)
    int gid = lane >> 2, tig = lane & 3;
    int m0 = blockIdx.x * 64;
    int n0 = blockIdx.y * 64;

    float acc[2][4][4];
#pragma unroll
    for (int i = 0; i < 2; i++)
#pragma unroll
        for (int j = 0; j < 4; j++)
#pragma unroll
            for (int q = 0; q < 4; q++) acc[i][j][q] = 0.f;

    int ar = tid >> 1;            // A row 0..63
    int akc = (tid & 1) * 16;     // A k chunk base
    int bkr = tid >> 2;           // B k row 0..31
    int bnc = (tid & 3) * 16;     // B n chunk base

    for (int kt = 0; kt < K; kt += 32) {
        // A tile: 64 x 32, split hi/lo at store
#pragma unroll
        for (int u = 0; u < 4; u++) {
            float4 v = *(const float4*)(A + (long)(m0 + ar) * K + kt + akc + u * 4);
            float vv[4] = {v.x, v.y, v.z, v.w};
#pragma unroll
            for (int q = 0; q < 4; q++) {
                uint32_t hi = f2tf32(vv[q]);
                AsH[(akc + u * 4 + q) * TS + ar] = hi;
                AsL[(akc + u * 4 + q) * TS + ar] = f2tf32(vv[q] - __uint_as_float(hi));
            }
        }
        // B tile: 32 x 64
#pragma unroll
        for (int u = 0; u < 4; u++) {
            float4 v = *(const float4*)(W + (long)(kt + bkr) * NC + n0 + bnc + u * 4);
            float vv[4] = {v.x, v.y, v.z, v.w};
#pragma unroll
            for (int q = 0; q < 4; q++) {
                uint32_t hi = f2tf32(vv[q]);
                BsH[bkr * TS + bnc + u * 4 + q] = hi;
                BsL[bkr * TS + bnc + u * 4 + q] = f2tf32(vv[q] - __uint_as_float(hi));
            }
        }
        __syncthreads();

#pragma unroll
        for (int kk = 0; kk < 4; kk++) {
            int k0 = kk * 8;
            uint32_t aH[2][4], aL[2][4];
#pragma unroll
            for (int mi = 0; mi < 2; mi++) {
                int m = wm * 32 + mi * 16;
                int i0 = (k0 + tig) * TS + m + gid;
                int i1 = (k0 + tig + 4) * TS + m + gid;
                aH[mi][0] = AsH[i0];     aL[mi][0] = AsL[i0];
                aH[mi][1] = AsH[i0 + 8]; aL[mi][1] = AsL[i0 + 8];
                aH[mi][2] = AsH[i1];     aL[mi][2] = AsL[i1];
                aH[mi][3] = AsH[i1 + 8]; aL[mi][3] = AsL[i1 + 8];
            }
            uint32_t bH[4][2], bL[4][2];
#pragma unroll
            for (int nj = 0; nj < 4; nj++) {
                int n = wn * 32 + nj * 8;
                int i0 = (k0 + tig) * TS + n + gid;
                int i1 = (k0 + tig + 4) * TS + n + gid;
                bH[nj][0] = BsH[i0]; bH[nj][1] = BsH[i1];
                bL[nj][0] = BsL[i0]; bL[nj][1] = BsL[i1];
            }
#pragma unroll
            for (int mi = 0; mi < 2; mi++)
#pragma unroll
                for (int nj = 0; nj < 4; nj++) {
                    // small cross terms first, then the dominant hi*hi
                    MMA_TF32(acc[mi][nj], aH[mi][0], aH[mi][1], aH[mi][2], aH[mi][3],
                             bL[nj][0], bL[nj][1]);
                    MMA_TF32(acc[mi][nj], aL[mi][0], aL[mi][1], aL[mi][2], aL[mi][3],
                             bH[nj][0], bH[nj][1]);
                    MMA_TF32(acc[mi][nj], aH[mi][0], aH[mi][1], aH[mi][2], aH[mi][3],
                             bH[nj][0], bH[nj][1]);
                }
        }
        __syncthreads();
    }

    // epilogue: c0 (row=gid, col=2*tig), c1 (+1 col), c2 (row=gid+8), c3
#pragma unroll
    for (int mi = 0; mi < 2; mi++) {
        int r0 = m0 + wm * 32 + mi * 16 + gid;
#pragma unroll
        for (int nj = 0; nj < 4; nj++) {
            int col = n0 + wn * 32 + nj * 8 + 2 * tig;
            float bi0 = bias[col], bi1 = bias[col + 1];
            float v0 = acc[mi][nj][0] + bi0;
            float v1 = acc[mi][nj][1] + bi1;
            float v2 = acc[mi][nj][2] + bi0;
            float v3 = acc[mi][nj][3] + bi1;
            if (do_relu) {
                v0 = fmaxf(v0, 0.f); v1 = fmaxf(v1, 0.f);
                v2 = fmaxf(v2, 0.f); v3 = fmaxf(v3, 0.f);
            }
            *(float2*)(C + (long)r0 * NC + col)       = make_float2(v0, v1);
            *(float2*)(C + (long)(r0 + 8) * NC + col) = make_float2(v2, v3);
        }
    }
}

// ---------------- BN stats: per-block partial sums ----------------
__global__ void bn_stats_kernel() {
    int d = threadIdx.x;               // 128 threads, one channel each
    int r0 = blockIdx.x * 256;
    int r1 = r0 + 256; if (r1 > NN) r1 = NN;
    float s = 0.f, sq = 0.f;
    for (int r = r0; r < r1; r++) {
        float v = g_z2[(long)r * D + d];
        s += v; sq += v * v;
    }
    g_part[(blockIdx.x * 2 + 0) * D + d] = s;
    g_part[(blockIdx.x * 2 + 1) * D + d] = sq;
}

__global__ void bn_finalize_kernel() {
    int d = threadIdx.x;
    float s = 0.f, sq = 0.f;
    for (int b = 0; b < STATS_BLKS; b++) {
        s  += g_part[(b * 2 + 0) * D + d];
        sq += g_part[(b * 2 + 1) * D + d];
    }
    float mu = s * (1.0f / NN);
    float var = sq * (1.0f / NN) - mu * mu;
    g_mu[d] = mu;
    g_rsig[d] = rsqrtf(var + BN_EPS);
}

// ---------------- BN apply (+relu) ; last layer: write node_rep + pool RED ----------------
__global__ void bn_apply_kernel(const float* __restrict__ gamma,
                                const float* __restrict__ beta,
                                const int* __restrict__ batch_ids,
                                float* __restrict__ out_node,
                                int is_last) {
    int idx = blockIdx.x * blockDim.x + threadIdx.x;   // over NN*32 float4s
    if (idx >= NN * 32) return;
    int row = idx >> 5;
    int c4  = idx & 31;
    int d0  = c4 * 4;
    float4 x = *(const float4*)(g_z2 + (long)row * D + d0);
    float4 o;
    float* xv = (float*)&x;
    float* ov = (float*)&o;
#pragma unroll
    for (int j = 0; j < 4; j++) {
        int d = d0 + j;
        float v = gamma[d] * (xv[j] - g_mu[d]) * g_rsig[d] + beta[d];
        if (!is_last) v = fmaxf(v, 0.f);   // relu on all but last layer
        ov[j] = v;
    }
    if (!is_last) {
        *(float4*)(g_h + (long)row * D + d0) = o;
        *(float4*)(g_z + (long)row * D + d0) = o;   // init z=h for next layer
    } else {
        *(float4*)(out_node + (long)row * D + d0) = o;   // node_rep output
        int b = batch_ids[row];
        float* gp = g_gsum + (long)b * D + d0;
        asm volatile("red.global.add.v4.f32 [%0], {%1,%2,%3,%4};"
                     :: "l"(gp), "f"(o.x), "f"(o.y), "f"(o.z), "f"(o.w) : "memory");
    }
}

__global__ void pool_finalize_kernel(float* __restrict__ out) {
    int i = blockIdx.x * blockDim.x + threadIdx.x;   // over GG*D
    if (i >= GG * D) return;
    int g = i >> 7;
    out[i] = g_gsum[i] / fmaxf(g_gcnt[g], 1.0f);
}

// ---------------- launch ----------------
extern "C" void kernel_launch(void* const* d_in, const int* in_sizes, int n_in,
                              void* d_out, int out_size) {
    const int* x_tokens   = (const int*)d_in[0];
    const int* ins_len    = (const int*)d_in[1];
    const int* edge_index = (const int*)d_in[2];
    const int* edge_attr  = (const int*)d_in[3];
    const int* batch_ids  = (const int*)d_in[4];
    const float* wemb  = (const float*)d_in[5];
    const float* eemb  = (const float*)d_in[6];
    const float* W1    = (const float*)d_in[7];
    const float* b1    = (const float*)d_in[8];
    const float* W2    = (const float*)d_in[9];
    const float* b2    = (const float*)d_in[10];
    const float* gamma = (const float*)d_in[11];
    const float* beta  = (const float*)d_in[12];
    float* out = (float*)d_out;
    float* out_graph = out;                 // [GG, D]
    float* out_node  = out + GG * D;        // [NN, D]

    float *pz, *pmid, *pz2;
    cudaGetSymbolAddress((void**)&pz,   g_z);
    cudaGetSymbolAddress((void**)&pmid, g_mid);
    cudaGetSymbolAddress((void**)&pz2,  g_z2);

    // WordBag -> h, z
    wordbag_kernel<<<NN, 128>>>(x_tokens, ins_len, wemb);
    // pool prep (counts depend only on batch_ids)
    zero_pool_kernel<<<(GG * D + 255) / 256, 256>>>();
    count_kernel<<<(NN + 255) / 256, 256>>>(batch_ids);

    for (int l = 0; l < NLAYERS; l++) {
        int is_last = (l == NLAYERS - 1);
        // z += scatter(h[src] + e)
        scatter_kernel<<<(NE + 7) / 8, 256>>>(edge_index, edge_attr, eemb);
        // mid = relu(z @ W1[l] + b1[l])   [NN, 256]
        gemm_3xtf32_kernel<<<dim3(NN / 64, D2 / 64), 128>>>(
            pz, W1 + (long)l * D * D2, b1 + (long)l * D2, pmid, D, D2, 1);
        // z2 = mid @ W2[l] + b2[l]        [NN, 128]
        gemm_3xtf32_kernel<<<dim3(NN / 64, D / 64), 128>>>(
            pmid, W2 + (long)l * D2 * D, b2 + (long)l * D, pz2, D2, D, 0);
        // BN train-stats + apply (+relu unless last); last layer also pools
        bn_stats_kernel<<<STATS_BLKS, D>>>();
        bn_finalize_kernel<<<1, D>>>();
        bn_apply_kernel<<<(NN * 32 + 255) / 256, 256>>>(
            gamma + (long)l * D, beta + (long)l * D, batch_ids, out_node, is_last);
    }

    pool_finalize_kernel<<<(GG * D + 255) / 256, 256>>>(out_graph);
}

// round 5
// speedup vs baseline: 1.1949x; 1.1949x over previous
#include <cuda_runtime.h>
#include <cstdint>

#define NN 40000        // nodes (== 625 * 64)
#define NE 640000       // edges
#define D 128
#define D2 256
#define LTOK 10
#define NLAYERS 5
#define GG 512          // graphs
#define BN_EPS 1e-5f
#define STATS_BLKS 157  // ceil(NN/256)

// ---------------- scratch (static device globals; no allocation) ----------------
__device__ float g_h[NN * D];
__device__ float g_z[NN * D];
__device__ float g_mid[NN * D2];
__device__ float g_z2[NN * D];
__device__ float g_part[STATS_BLKS * 2 * D];
__device__ float g_mu[D];
__device__ float g_rsig[D];
__device__ float g_gsum[GG * D];
__device__ float g_gcnt[GG];
// CSR (by dst)
__device__ int g_deg[NN];
__device__ int g_off[NN + 1];
__device__ int g_cursor[NN];
__device__ int g_csr[NE];            // src*16 + edge_type
// fragment-packed tf32 hi/lo weights (see wsplit for layout)
__device__ float g_w1_hi[NLAYERS * D * D2], g_w1_lo[NLAYERS * D * D2];
__device__ float g_w2_hi[NLAYERS * D2 * D], g_w2_lo[NLAYERS * D2 * D];

// ---------------- helpers ----------------
__device__ __forceinline__ uint32_t f2tf32(float v) {
    uint32_t u;
    asm("cvt.rna.tf32.f32 %0, %1;" : "=r"(u) : "f"(v));
    return u;
}

#define MMA_TF32(ACC, A0, A1, A2, A3, B0, B1)                                  \
    asm volatile(                                                              \
        "mma.sync.aligned.m16n8k8.row.col.f32.tf32.tf32.f32 "                  \
        "{%0,%1,%2,%3}, {%4,%5,%6,%7}, {%8,%9}, {%0,%1,%2,%3};"                \
        : "+f"(ACC[0]), "+f"(ACC[1]), "+f"(ACC[2]), "+f"(ACC[3])               \
        : "r"(A0), "r"(A1), "r"(A2), "r"(A3), "r"(B0), "r"(B1))

// ---------------- WordBag ----------------
__global__ void wordbag_kernel(const int* __restrict__ x_tokens,
                               const int* __restrict__ ins_len,
                               const float* __restrict__ wemb) {
    int n = blockIdx.x;
    int d = threadIdx.x;
    __shared__ int toks[LTOK];
    __shared__ int len_s;
    if (d < LTOK) toks[d] = x_tokens[n * LTOK + d];
    if (d == 0) len_s = ins_len[n];
    __syncthreads();
    int len = len_s;
    float acc = 0.f;
    for (int l = 0; l < len; l++)
        acc += wemb[(long)toks[l] * D + d];
    g_h[n * D + d] = acc / (float)len;
}

// ---------------- pool prep ----------------
__global__ void zero_pool_kernel() {
    int i = blockIdx.x * blockDim.x + threadIdx.x;
    if (i < GG * D) g_gsum[i] = 0.f;
    if (i < GG) g_gcnt[i] = 0.f;
    if (i < NN) g_deg[i] = 0;
}
__global__ void count_kernel(const int* __restrict__ batch_ids) {
    int i = blockIdx.x * blockDim.x + threadIdx.x;
    if (i < NN) atomicAdd(&g_gcnt[batch_ids[i]], 1.0f);
}

// ---------------- CSR build (edge structure is launch-constant) ----------------
__global__ void hist_kernel(const int* __restrict__ edge_index) {
    int e = blockIdx.x * blockDim.x + threadIdx.x;
    if (e < NE) atomicAdd(&g_deg[edge_index[NE + e]], 1);
}
__global__ void scan_kernel() {    // 1 block, 1024 threads; 40 elems/thread
    __shared__ int ssum[1024];
    int tid = threadIdx.x;
    int s = 0;
#pragma unroll 4
    for (int i = 0; i < 40; i++) {
        int idx = tid * 40 + i;
        if (idx < NN) s += g_deg[idx];
    }
    ssum[tid] = s;
    __syncthreads();
    for (int off = 1; off < 1024; off <<= 1) {
        int v = (tid >= off) ? ssum[tid - off] : 0;
        __syncthreads();
        ssum[tid] += v;
        __syncthreads();
    }
    int run = (tid > 0) ? ssum[tid - 1] : 0;
    for (int i = 0; i < 40; i++) {
        int idx = tid * 40 + i;
        if (idx < NN) {
            g_off[idx] = run;
            g_cursor[idx] = run;
            run += g_deg[idx];
        }
    }
    if (tid == 1023) g_off[NN] = NE;
}
__global__ void fill_kernel(const int* __restrict__ edge_index,
                            const int* __restrict__ edge_attr) {
    int e = blockIdx.x * blockDim.x + threadIdx.x;
    if (e >= NE) return;
    int dst = edge_index[NE + e];
    int pos = atomicAdd(&g_cursor[dst], 1);
    g_csr[pos] = edge_index[e] * 16 + edge_attr[e];
}

// ---------------- aggregation: z[n] = h[n] + sum_in (h[src] + e[et]) ----------------
// one warp per node; lane owns 4 channels (float4)
__global__ void aggregate_kernel(const float* __restrict__ eemb) {
    int warp = (blockIdx.x * blockDim.x + threadIdx.x) >> 5;
    int lane = threadIdx.x & 31;
    if (warp >= NN) return;
    int n = warp;
    float4 acc = *(const float4*)(g_h + (long)n * D + lane * 4);
    int s = g_off[n], e = g_off[n + 1];
    for (int i = s; i < e; i++) {
        int p = g_csr[i];
        float4 hv = *(const float4*)(g_h + (long)(p >> 4) * D + lane * 4);
        float4 ev = __ldg((const float4*)(eemb + (p & 15) * D + lane * 4));
        acc.x += hv.x + ev.x; acc.y += hv.y + ev.y;
        acc.z += hv.z + ev.z; acc.w += hv.w + ev.w;
    }
    *(float4*)(g_z + (long)n * D + lane * 4) = acc;
}

// ---------------- weight pre-pack: transpose + tf32 hi/lo split + fragment layout ----------------
// dest idx (within layer) = ((((nb*(KD/32) + kc)*4 + kk)*8 + nj8)*32 + lane)*2 + reg
// nb=n>>6, kc=k>>5, kk=(k>>3)&3, k8=k&7, reg=k8>>2, tig=k8&3, gid=n&7, nj8=(n>>3)&7, lane=gid*4+tig
__global__ void wsplit_kernel(const float* __restrict__ W1, const float* __restrict__ W2) {
    int idx = blockIdx.x * blockDim.x + threadIdx.x;
    const int T1 = NLAYERS * D * D2;
    if (idx < T1) {            // W1: [l][k:128][n:256], KD=128
        int l = idx / (D * D2), r = idx % (D * D2);
        int k = r / D2, n = r % D2;
        float v = W1[idx];
        int nb = n >> 6, kc = k >> 5, kk = (k >> 3) & 3, k8 = k & 7;
        int lane = (n & 7) * 4 + (k8 & 3);
        int dest = l * D * D2 +
                   (((((nb * 4 + kc) * 4 + kk) * 8 + ((n >> 3) & 7)) * 32 + lane) * 2 + (k8 >> 2));
        uint32_t h = f2tf32(v);
        g_w1_hi[dest] = __uint_as_float(h);
        g_w1_lo[dest] = __uint_as_float(f2tf32(v - __uint_as_float(h)));
    } else if (idx < 2 * T1) { // W2: [l][k:256][n:128], KD=256
        int j = idx - T1;
        int l = j / (D2 * D), r = j % (D2 * D);
        int k = r / D, n = r % D;
        float v = W2[j];
        int nb = n >> 6, kc = k >> 5, kk = (k >> 3) & 3, k8 = k & 7;
        int lane = (n & 7) * 4 + (k8 & 3);
        int dest = l * D2 * D +
                   (((((nb * 8 + kc) * 4 + kk) * 8 + ((n >> 3) & 7)) * 32 + lane) * 2 + (k8 >> 2));
        uint32_t h = f2tf32(v);
        g_w2_hi[dest] = __uint_as_float(h);
        g_w2_lo[dest] = __uint_as_float(f2tf32(v - __uint_as_float(h)));
    }
}

// ---------------- 3xTF32 GEMM, fragment-packed smem ----------------
// C[M,NT] = act(A @ W^T + bias); BM=64, BN=64, BK=32; 128 threads (4 warps 2x2)
template<int NT, int KD>
__global__ void __launch_bounds__(128)
gemm_tc_kernel(const float* __restrict__ A, const float* __restrict__ Bhi,
               const float* __restrict__ Blo, const float* __restrict__ bias,
               float* __restrict__ C, int do_relu) {
    // A packed: [kk:4][t:4][lane:32][reg:4] floats; hi at 0, lo at +2048
    // B packed: [kk:4][nj8:8][lane:32][reg:2] floats; hi at 0, lo at +2048
    __shared__ float As[4096];
    __shared__ float Bs[4096];
    int tid = threadIdx.x, lane = tid & 31, warp = tid >> 5;
    int wm = warp >> 1, wn = warp & 1;
    int m0 = blockIdx.x * 64;
    int nb = blockIdx.y;
    int n0 = nb * 64;

    float acc[2][4][4];
#pragma unroll
    for (int i = 0; i < 2; i++)
#pragma unroll
        for (int j = 0; j < 4; j++)
#pragma unroll
            for (int q = 0; q < 4; q++) acc[i][j][q] = 0.f;

    int r = tid >> 1, c4b = (tid & 1) * 4;
    int gidw = r & 7, rh = (r >> 3) & 1, tt = r >> 4;

    for (int kc = 0; kc < KD / 32; kc++) {
        if (kc) __syncthreads();
        // fill A (split hi/lo into fragment layout)
#pragma unroll
        for (int q = 0; q < 4; q++) {
            int c4 = c4b + q;
            int kk = c4 >> 1, ch = c4 & 1;
            int reg = ch * 2 + rh;
            float4 v = *(const float4*)(A + (long)(m0 + r) * KD + kc * 32 + c4 * 4);
            float vv[4] = {v.x, v.y, v.z, v.w};
            int base = ((kk * 4 + tt) * 32 + gidw * 4) * 4 + reg;
#pragma unroll
            for (int j = 0; j < 4; j++) {
                uint32_t h = f2tf32(vv[j]);
                As[base + j * 4] = __uint_as_float(h);
                As[2048 + base + j * 4] = __uint_as_float(f2tf32(vv[j] - __uint_as_float(h)));
            }
        }
        // copy B (pre-packed): 2048 floats hi + 2048 lo
        {
            const float4* bh = (const float4*)(Bhi + ((long)nb * (KD / 32) + kc) * 2048);
            const float4* bl = (const float4*)(Blo + ((long)nb * (KD / 32) + kc) * 2048);
#pragma unroll
            for (int i = 0; i < 4; i++) {
                ((float4*)Bs)[tid + i * 128] = bh[tid + i * 128];
                ((float4*)(Bs + 2048))[tid + i * 128] = bl[tid + i * 128];
            }
        }
        __syncthreads();
#pragma unroll
        for (int kk = 0; kk < 4; kk++) {
            uint32_t aH[2][4], aL[2][4];
#pragma unroll
            for (int mi = 0; mi < 2; mi++) {
                int t = wm * 2 + mi;
                const uint4 h = *(const uint4*)&As[((kk * 4 + t) * 32 + lane) * 4];
                const uint4 l = *(const uint4*)&As[2048 + ((kk * 4 + t) * 32 + lane) * 4];
                aH[mi][0] = h.x; aH[mi][1] = h.y; aH[mi][2] = h.z; aH[mi][3] = h.w;
                aL[mi][0] = l.x; aL[mi][1] = l.y; aL[mi][2] = l.z; aL[mi][3] = l.w;
            }
            uint32_t bH[4][2], bL[4][2];
#pragma unroll
            for (int nj = 0; nj < 4; nj++) {
                int nj8 = wn * 4 + nj;
                const uint2 h = *(const uint2*)&Bs[((kk * 8 + nj8) * 32 + lane) * 2];
                const uint2 l = *(const uint2*)&Bs[2048 + ((kk * 8 + nj8) * 32 + lane) * 2];
                bH[nj][0] = h.x; bH[nj][1] = h.y;
                bL[nj][0] = l.x; bL[nj][1] = l.y;
            }
#pragma unroll
            for (int mi = 0; mi < 2; mi++)
#pragma unroll
                for (int nj = 0; nj < 4; nj++) {
                    MMA_TF32(acc[mi][nj], aH[mi][0], aH[mi][1], aH[mi][2], aH[mi][3],
                             bL[nj][0], bL[nj][1]);
                    MMA_TF32(acc[mi][nj], aL[mi][0], aL[mi][1], aL[mi][2], aL[mi][3],
                             bH[nj][0], bH[nj][1]);
                    MMA_TF32(acc[mi][nj], aH[mi][0], aH[mi][1], aH[mi][2], aH[mi][3],
                             bH[nj][0], bH[nj][1]);
                }
        }
    }

    // epilogue
    int gid = lane >> 2, tig = lane & 3;
#pragma unroll
    for (int mi = 0; mi < 2; mi++) {
        int r0 = m0 + wm * 32 + mi * 16 + gid;
#pragma unroll
        for (int nj = 0; nj < 4; nj++) {
            int col = n0 + wn * 32 + nj * 8 + 2 * tig;
            float bi0 = bias[col], bi1 = bias[col + 1];
            float v0 = acc[mi][nj][0] + bi0;
            float v1 = acc[mi][nj][1] + bi1;
            float v2 = acc[mi][nj][2] + bi0;
            float v3 = acc[mi][nj][3] + bi1;
            if (do_relu) {
                v0 = fmaxf(v0, 0.f); v1 = fmaxf(v1, 0.f);
                v2 = fmaxf(v2, 0.f); v3 = fmaxf(v3, 0.f);
            }
            *(float2*)(C + (long)r0 * NT + col)       = make_float2(v0, v1);
            *(float2*)(C + (long)(r0 + 8) * NT + col) = make_float2(v2, v3);
        }
    }
}

// ---------------- BN ----------------
__global__ void bn_stats_kernel() {
    int d = threadIdx.x;
    int r0 = blockIdx.x * 256;
    int r1 = r0 + 256; if (r1 > NN) r1 = NN;
    float s = 0.f, sq = 0.f;
    for (int r = r0; r < r1; r++) {
        float v = g_z2[(long)r * D + d];
        s += v; sq += v * v;
    }
    g_part[(blockIdx.x * 2 + 0) * D + d] = s;
    g_part[(blockIdx.x * 2 + 1) * D + d] = sq;
}
__global__ void bn_finalize_kernel() {
    int d = threadIdx.x;
    float s = 0.f, sq = 0.f;
    for (int b = 0; b < STATS_BLKS; b++) {
        s  += g_part[(b * 2 + 0) * D + d];
        sq += g_part[(b * 2 + 1) * D + d];
    }
    float mu = s * (1.0f / NN);
    float var = sq * (1.0f / NN) - mu * mu;
    g_mu[d] = mu;
    g_rsig[d] = rsqrtf(var + BN_EPS);
}
__global__ void bn_apply_kernel(const float* __restrict__ gamma,
                                const float* __restrict__ beta,
                                const int* __restrict__ batch_ids,
                                float* __restrict__ out_node,
                                int is_last) {
    int idx = blockIdx.x * blockDim.x + threadIdx.x;
    if (idx >= NN * 32) return;
    int row = idx >> 5;
    int d0  = (idx & 31) * 4;
    float4 x = *(const float4*)(g_z2 + (long)row * D + d0);
    float4 o;
    float* xv = (float*)&x;
    float* ov = (float*)&o;
#pragma unroll
    for (int j = 0; j < 4; j++) {
        int d = d0 + j;
        float v = gamma[d] * (xv[j] - g_mu[d]) * g_rsig[d] + beta[d];
        if (!is_last) v = fmaxf(v, 0.f);
        ov[j] = v;
    }
    if (!is_last) {
        *(float4*)(g_h + (long)row * D + d0) = o;
    } else {
        *(float4*)(out_node + (long)row * D + d0) = o;
        int b = batch_ids[row];
        float* gp = g_gsum + (long)b * D + d0;
        asm volatile("red.global.add.v4.f32 [%0], {%1,%2,%3,%4};"
                     :: "l"(gp), "f"(o.x), "f"(o.y), "f"(o.z), "f"(o.w) : "memory");
    }
}
__global__ void pool_finalize_kernel(float* __restrict__ out) {
    int i = blockIdx.x * blockDim.x + threadIdx.x;
    if (i >= GG * D) return;
    int g = i >> 7;
    out[i] = g_gsum[i] / fmaxf(g_gcnt[g], 1.0f);
}

// ---------------- launch ----------------
extern "C" void kernel_launch(void* const* d_in, const int* in_sizes, int n_in,
                              void* d_out, int out_size) {
    const int* x_tokens   = (const int*)d_in[0];
    const int* ins_len    = (const int*)d_in[1];
    const int* edge_index = (const int*)d_in[2];
    const int* edge_attr  = (const int*)d_in[3];
    const int* batch_ids  = (const int*)d_in[4];
    const float* wemb  = (const float*)d_in[5];
    const float* eemb  = (const float*)d_in[6];
    const float* W1    = (const float*)d_in[7];
    const float* b1    = (const float*)d_in[8];
    const float* W2    = (const float*)d_in[9];
    const float* b2    = (const float*)d_in[10];
    const float* gamma = (const float*)d_in[11];
    const float* beta  = (const float*)d_in[12];
    float* out = (float*)d_out;
    float* out_graph = out;                 // [GG, D]
    float* out_node  = out + GG * D;        // [NN, D]

    float *pz, *pmid, *pz2, *pw1h, *pw1l, *pw2h, *pw2l;
    cudaGetSymbolAddress((void**)&pz,   g_z);
    cudaGetSymbolAddress((void**)&pmid, g_mid);
    cudaGetSymbolAddress((void**)&pz2,  g_z2);
    cudaGetSymbolAddress((void**)&pw1h, g_w1_hi);
    cudaGetSymbolAddress((void**)&pw1l, g_w1_lo);
    cudaGetSymbolAddress((void**)&pw2h, g_w2_hi);
    cudaGetSymbolAddress((void**)&pw2l, g_w2_lo);

    wordbag_kernel<<<NN, 128>>>(x_tokens, ins_len, wemb);
    zero_pool_kernel<<<(GG * D + 255) / 256, 256>>>();
    count_kernel<<<(NN + 255) / 256, 256>>>(batch_ids);
    wsplit_kernel<<<(2 * NLAYERS * D * D2 + 255) / 256, 256>>>(W1, W2);
    // CSR build
    hist_kernel<<<(NE + 255) / 256, 256>>>(edge_index);
    scan_kernel<<<1, 1024>>>();
    fill_kernel<<<(NE + 255) / 256, 256>>>(edge_index, edge_attr);

    for (int l = 0; l < NLAYERS; l++) {
        int is_last = (l == NLAYERS - 1);
        aggregate_kernel<<<NN / 8, 256>>>(eemb);
        gemm_tc_kernel<D2, D><<<dim3(NN / 64, 4), 128>>>(
            pz, pw1h + (long)l * D * D2, pw1l + (long)l * D * D2,
            b1 + (long)l * D2, pmid, 1);
        gemm_tc_kernel<D, D2><<<dim3(NN / 64, 2), 128>>>(
            pmid, pw2h + (long)l * D2 * D, pw2l + (long)l * D2 * D,
            b2 + (long)l * D, pz2, 0);
        bn_stats_kernel<<<STATS_BLKS, D>>>();
        bn_finalize_kernel<<<1, D>>>();
        bn_apply_kernel<<<(NN * 32 + 255) / 256, 256>>>(
            gamma + (long)l * D, beta + (long)l * D, batch_ids, out_node, is_last);
    }

    pool_finalize_kernel<<<(GG * D + 255) / 256, 256>>>(out_graph);
}